// round 2
// baseline (speedup 1.0000x reference)
#include <cuda_runtime.h>

#define N_NODES 160000
#define NODES_PER_GRAPH 20000
#define NBATCH 8
#define N_EDGES 5120000
#define HID 16
#define K1 20000
#define TK 1250

// ---------------- device scratch (no allocation allowed) ----------------
__device__ float d_s1[N_NODES];            // layer-1 scalar aggregation (zero invariant)
__device__ float d_p[N_NODES];             // h . Wr2 per node
__device__ float d_gt[N_NODES];            // h2 transposed: [20000][8]
__device__ float d_y1[4000 * NBATCH];      // layer outputs, transposed [J][8]
__device__ float d_y2[800 * NBATCH];
__device__ float d_y3[160 * NBATCH];

// ---------------- kernels ----------------

// pass 1: s1[tgt] += ew * x[src]
__global__ void edge_pass1(const int* __restrict__ src, const int* __restrict__ tgt,
                           const float* __restrict__ ew, const float* __restrict__ x) {
    int i = blockIdx.x * blockDim.x + threadIdx.x;
    int base = i * 4;
    if (base >= N_EDGES) return;
    int4   s = *(const int4*)(src + base);
    int4   t = *(const int4*)(tgt + base);
    float4 w = *(const float4*)(ew + base);
    atomicAdd(&d_s1[t.x], w.x * __ldg(&x[s.x]));
    atomicAdd(&d_s1[t.y], w.y * __ldg(&x[s.y]));
    atomicAdd(&d_s1[t.z], w.z * __ldg(&x[s.z]));
    atomicAdd(&d_s1[t.w], w.w * __ldg(&x[s.w]));
}

// per node: compute p[n] (for pass 2), init gt with q[n] + br2, and re-zero s1
// (re-zeroing here maintains the "s1 == 0 at kernel_launch entry" invariant
//  across graph replays, removing the separate zeroing kernel).
__global__ void node_kernel(const float* __restrict__ x,
                            const float* __restrict__ Wr1, const float* __restrict__ br1,
                            const float* __restrict__ Ws1, const float* __restrict__ Wr2,
                            const float* __restrict__ br2, const float* __restrict__ Ws2) {
    int n = blockIdx.x * blockDim.x + threadIdx.x;
    if (n >= N_NODES) return;
    float s  = d_s1[n];
    d_s1[n] = 0.f;
    float xv = x[n];
    float pa = 0.f, qa = 0.f;
#pragma unroll
    for (int f = 0; f < HID; f++) {
        float h = fmaf(s, __ldg(&Wr1[f]), fmaf(xv, __ldg(&Ws1[f]), __ldg(&br1[f])));
        h = fmaxf(h, 0.f);
        pa = fmaf(__ldg(&Wr2[f]), h, pa);
        qa = fmaf(__ldg(&Ws2[f]), h, qa);
    }
    d_p[n] = pa;
    unsigned nu = (unsigned)n;
    unsigned b  = nu / NODES_PER_GRAPH;
    unsigned k  = nu - b * NODES_PER_GRAPH;
    d_gt[k * NBATCH + b] = qa + __ldg(&br2[0]);
}

// pass 2: gt[transposed(tgt)] += ew * p[src]
__global__ void edge_pass2(const int* __restrict__ src, const int* __restrict__ tgt,
                           const float* __restrict__ ew) {
    int i = blockIdx.x * blockDim.x + threadIdx.x;
    int base = i * 4;
    if (base >= N_EDGES) return;
    int4   s = *(const int4*)(src + base);
    int4   t = *(const int4*)(tgt + base);
    float4 w = *(const float4*)(ew + base);
#define EP2_ONE(SS, TT, WW)                                            \
    {                                                                  \
        unsigned tu = (unsigned)(TT);                                  \
        unsigned b  = tu / NODES_PER_GRAPH;                            \
        unsigned k  = tu - b * NODES_PER_GRAPH;                        \
        atomicAdd(&d_gt[k * NBATCH + b], (WW) * __ldg(&d_p[SS]));      \
    }
    EP2_ONE(s.x, t.x, w.x);
    EP2_ONE(s.y, t.y, w.y);
    EP2_ONE(s.z, t.z, w.z);
    EP2_ONE(s.w, t.w, w.w);
#undef EP2_ONE
}

// ---- GEMM1: y1[j][b] = relu(b1[j] + sum_k W1[j,k] * gt[k][b]) ----
// 125 blocks x 512 threads, 32 rows per block (2 rows per warp).
// g staged in shared memory in 16 even K-tiles of 1250 (40KB, padded rows).
__global__ void __launch_bounds__(512) gemm1_kernel(const float* __restrict__ W,
                                                    const float* __restrict__ bias) {
    __shared__ float gs[8][TK + 1];
    int tid  = threadIdx.x;
    int lane = tid & 31;
    int wid  = tid >> 5;           // 16 warps
    int j0   = blockIdx.x * 32;
    int r0   = wid * 2;            // this warp owns rows j0+r0, j0+r0+1

    const float* Wr0 = W + (size_t)(j0 + r0) * K1;
    const float* Wr1 = W + (size_t)(j0 + r0 + 1) * K1;

    float acc[2][8];
#pragma unroll
    for (int r = 0; r < 2; r++)
#pragma unroll
        for (int b = 0; b < 8; b++) acc[r][b] = 0.f;

    for (int kt = 0; kt < K1; kt += TK) {
        __syncthreads();
        // stage tile: TK*8 floats = TK*2 float4 loads
        const float4* gin4 = (const float4*)(d_gt + (size_t)kt * 8);
        for (int i = tid; i < TK * 2; i += 512) {
            float4 v = __ldg(gin4 + i);
            int kk = i >> 1;
            int b0 = (i & 1) * 4;
            gs[b0 + 0][kk] = v.x;
            gs[b0 + 1][kk] = v.y;
            gs[b0 + 2][kk] = v.z;
            gs[b0 + 3][kk] = v.w;
        }
        __syncthreads();

        for (int kk = lane; kk < TK; kk += 32) {
            float w0 = __ldg(Wr0 + kt + kk);
            float w1 = __ldg(Wr1 + kt + kk);
#pragma unroll
            for (int b = 0; b < 8; b++) {
                float g = gs[b][kk];
                acc[0][b] = fmaf(w0, g, acc[0][b]);
                acc[1][b] = fmaf(w1, g, acc[1][b]);
            }
        }
    }

    // warp-reduce the 16 (row,b) partials; lane r*8+b keeps its value
    float mine = 0.f;
#pragma unroll
    for (int r = 0; r < 2; r++)
#pragma unroll
        for (int b = 0; b < 8; b++) {
            float v = acc[r][b];
#pragma unroll
            for (int o = 16; o > 0; o >>= 1)
                v += __shfl_xor_sync(0xffffffffu, v, o);
            if (lane == r * 8 + b) mine = v;
        }
    if (lane < 16) {
        int r = lane >> 3;
        int b = lane & 7;
        int j = j0 + r0 + r;
        float v = mine + __ldg(&bias[j]);
        d_y1[j * 8 + b] = fmaxf(v, 0.f);
    }
}

// batch-8 GEMV for the small layers (2 and 3)
__global__ void gemm8(const float* __restrict__ W, const float* __restrict__ bias,
                      int which_in, int which_out, int K, int do_relu) {
    const float* __restrict__ gin  = (which_in == 1) ? d_y1 : d_y2;
    float* __restrict__       gout = (which_out == 1) ? d_y2 : d_y3;

    __shared__ float red[64][8];
    int j0 = blockIdx.x * 8;

    float acc[8][8];
#pragma unroll
    for (int j = 0; j < 8; j++)
#pragma unroll
        for (int b = 0; b < 8; b++) acc[j][b] = 0.f;

    for (int k = threadIdx.x; k < K; k += 256) {
        float4 ga = __ldg((const float4*)(gin + (size_t)k * 8));
        float4 gb = __ldg((const float4*)(gin + (size_t)k * 8 + 4));
        float g[8] = {ga.x, ga.y, ga.z, ga.w, gb.x, gb.y, gb.z, gb.w};
#pragma unroll
        for (int j = 0; j < 8; j++) {
            float w = __ldg(&W[(size_t)(j0 + j) * K + k]);
#pragma unroll
            for (int b = 0; b < 8; b++) acc[j][b] = fmaf(w, g[b], acc[j][b]);
        }
    }

    int lane = threadIdx.x & 31;
    int wid  = threadIdx.x >> 5;
#pragma unroll
    for (int j = 0; j < 8; j++) {
#pragma unroll
        for (int b = 0; b < 8; b++) {
            float v = acc[j][b];
#pragma unroll
            for (int o = 16; o > 0; o >>= 1)
                v += __shfl_down_sync(0xffffffffu, v, o);
            if (lane == 0) red[j * 8 + b][wid] = v;
        }
    }
    __syncthreads();
    if (threadIdx.x < 64) {
        int j = threadIdx.x >> 3;
        int b = threadIdx.x & 7;
        float v = 0.f;
#pragma unroll
        for (int w = 0; w < 8; w++) v += red[threadIdx.x][w];
        v += __ldg(&bias[j0 + j]);
        if (do_relu) v = fmaxf(v, 0.f);
        gout[(j0 + j) * 8 + b] = v;
    }
}

// final layer [8,160] @ W4^T [160,10] + b4, then log_softmax per row.
__global__ void final_kernel(const float* __restrict__ W4, const float* __restrict__ b4,
                             float* __restrict__ out) {
    int b    = threadIdx.x >> 5;   // batch (warp id)
    int lane = threadIdx.x & 31;
    float z = -1e30f;
    if (lane < 10) {
        float acc = __ldg(&b4[lane]);
#pragma unroll 8
        for (int k = 0; k < 160; k++)
            acc = fmaf(__ldg(&W4[lane * 160 + k]), d_y3[k * 8 + b], acc);
        z = acc;
    }
    float m = z;
#pragma unroll
    for (int o = 16; o > 0; o >>= 1)
        m = fmaxf(m, __shfl_xor_sync(0xffffffffu, m, o));
    float e = (lane < 10) ? __expf(z - m) : 0.f;
    float ssum = e;
#pragma unroll
    for (int o = 16; o > 0; o >>= 1)
        ssum += __shfl_xor_sync(0xffffffffu, ssum, o);
    if (lane < 10) out[b * 10 + lane] = z - m - __logf(ssum);
}

// ---------------- launch ----------------
extern "C" void kernel_launch(void* const* d_in, const int* in_sizes, int n_in,
                              void* d_out, int out_size) {
    const float* x   = (const float*)d_in[0];
    const float* ew  = (const float*)d_in[1];
    const float* Wr1 = (const float*)d_in[2];
    const float* br1 = (const float*)d_in[3];
    const float* Ws1 = (const float*)d_in[4];
    const float* Wr2 = (const float*)d_in[5];
    const float* br2 = (const float*)d_in[6];
    const float* Ws2 = (const float*)d_in[7];
    const float* W1  = (const float*)d_in[8];
    const float* b1  = (const float*)d_in[9];
    const float* W2  = (const float*)d_in[10];
    const float* b2  = (const float*)d_in[11];
    const float* W3  = (const float*)d_in[12];
    const float* b3  = (const float*)d_in[13];
    const float* W4  = (const float*)d_in[14];
    const float* b4  = (const float*)d_in[15];
    const int*   ei  = (const int*)d_in[16];
    const int* src = ei;
    const int* tgt = ei + N_EDGES;
    float* out = (float*)d_out;

    edge_pass1<<<(N_EDGES / 4 + 255) / 256, 256>>>(src, tgt, ew, x);
    node_kernel<<<(N_NODES + 255) / 256, 256>>>(x, Wr1, br1, Ws1, Wr2, br2, Ws2);
    edge_pass2<<<(N_EDGES / 4 + 255) / 256, 256>>>(src, tgt, ew);
    gemm1_kernel<<<125, 512>>>(W1, b1);            // 20000 -> 4000
    gemm8<<<100, 256>>>(W2, b2, 1, 1, 4000, 1);    // 4000 -> 800
    gemm8<<<20, 256>>>(W3, b3, 2, 2, 800, 1);      // 800 -> 160
    final_kernel<<<1, 256>>>(W4, b4, out);         // 160 -> 10 + log_softmax
}

// round 3
// speedup vs baseline: 1.3924x; 1.3924x over previous
#include <cuda_runtime.h>

#define N_NODES 160000
#define NODES_PER_GRAPH 20000
#define NBATCH 8
#define N_EDGES 5120000
#define HID 16

// ---------------- device scratch (no allocation allowed) ----------------
__device__ float d_s1[N_NODES];            // layer-1 scalar aggregation (zero invariant)
__device__ float d_p[N_NODES];             // h . Wr2 per node
__device__ float d_gt[N_NODES];            // h2 transposed: [20000][8]
__device__ float d_y1[4000 * NBATCH];      // layer outputs, transposed [J][8]
__device__ float d_y2[800 * NBATCH];
__device__ float d_y3[160 * NBATCH];

// ---------------- kernels ----------------

// pass 1: s1[tgt] += ew * x[src]
__global__ void edge_pass1(const int* __restrict__ src, const int* __restrict__ tgt,
                           const float* __restrict__ ew, const float* __restrict__ x) {
    int i = blockIdx.x * blockDim.x + threadIdx.x;
    int base = i * 4;
    if (base >= N_EDGES) return;
    int4   s = *(const int4*)(src + base);
    int4   t = *(const int4*)(tgt + base);
    float4 w = *(const float4*)(ew + base);
    atomicAdd(&d_s1[t.x], w.x * __ldg(&x[s.x]));
    atomicAdd(&d_s1[t.y], w.y * __ldg(&x[s.y]));
    atomicAdd(&d_s1[t.z], w.z * __ldg(&x[s.z]));
    atomicAdd(&d_s1[t.w], w.w * __ldg(&x[s.w]));
}

// per node: compute p[n] (for pass 2), init gt with q[n] + br2, and re-zero s1
// (maintains the "s1 == 0 at entry" invariant across graph replays).
__global__ void node_kernel(const float* __restrict__ x,
                            const float* __restrict__ Wr1, const float* __restrict__ br1,
                            const float* __restrict__ Ws1, const float* __restrict__ Wr2,
                            const float* __restrict__ br2, const float* __restrict__ Ws2) {
    int n = blockIdx.x * blockDim.x + threadIdx.x;
    if (n >= N_NODES) return;
    float s  = d_s1[n];
    d_s1[n] = 0.f;
    float xv = x[n];
    float pa = 0.f, qa = 0.f;
#pragma unroll
    for (int f = 0; f < HID; f++) {
        float h = fmaf(s, __ldg(&Wr1[f]), fmaf(xv, __ldg(&Ws1[f]), __ldg(&br1[f])));
        h = fmaxf(h, 0.f);
        pa = fmaf(__ldg(&Wr2[f]), h, pa);
        qa = fmaf(__ldg(&Ws2[f]), h, qa);
    }
    d_p[n] = pa;
    unsigned nu = (unsigned)n;
    unsigned b  = nu / NODES_PER_GRAPH;
    unsigned k  = nu - b * NODES_PER_GRAPH;
    d_gt[k * NBATCH + b] = qa + __ldg(&br2[0]);
}

// pass 2: gt[transposed(tgt)] += ew * p[src]
__global__ void edge_pass2(const int* __restrict__ src, const int* __restrict__ tgt,
                           const float* __restrict__ ew) {
    int i = blockIdx.x * blockDim.x + threadIdx.x;
    int base = i * 4;
    if (base >= N_EDGES) return;
    int4   s = *(const int4*)(src + base);
    int4   t = *(const int4*)(tgt + base);
    float4 w = *(const float4*)(ew + base);
#define EP2_ONE(SS, TT, WW)                                            \
    {                                                                  \
        unsigned tu = (unsigned)(TT);                                  \
        unsigned b  = tu / NODES_PER_GRAPH;                            \
        unsigned k  = tu - b * NODES_PER_GRAPH;                        \
        atomicAdd(&d_gt[k * NBATCH + b], (WW) * __ldg(&d_p[SS]));      \
    }
    EP2_ONE(s.x, t.x, w.x);
    EP2_ONE(s.y, t.y, w.y);
    EP2_ONE(s.z, t.z, w.z);
    EP2_ONE(s.w, t.w, w.w);
#undef EP2_ONE
}

// ---- batch-8 GEMV, float4-vectorized: 8 output rows per block ----
// out_t[j][b] = relu?( bias[j] + sum_k W[j,k] * in_t[k][b] )
// Per thread-iter: 8 LDG.128 of W + 8 LDG.128 of g + 256 FMA.
__global__ void __launch_bounds__(256) gemm8v(const float* __restrict__ W,
                                              const float* __restrict__ bias,
                                              int which, int K, int do_relu) {
    const float* __restrict__ gin =
        (which == 0) ? d_gt : (which == 1) ? d_y1 : d_y2;
    float* __restrict__ gout =
        (which == 0) ? d_y1 : (which == 1) ? d_y2 : d_y3;

    __shared__ float red[64][8];
    int j0 = blockIdx.x * 8;
    int K4 = K >> 2;

    const float4* Wv0 = (const float4*)(W + (size_t)(j0 + 0) * K);
    const float4* Wv1 = (const float4*)(W + (size_t)(j0 + 1) * K);
    const float4* Wv2 = (const float4*)(W + (size_t)(j0 + 2) * K);
    const float4* Wv3 = (const float4*)(W + (size_t)(j0 + 3) * K);
    const float4* Wv4 = (const float4*)(W + (size_t)(j0 + 4) * K);
    const float4* Wv5 = (const float4*)(W + (size_t)(j0 + 5) * K);
    const float4* Wv6 = (const float4*)(W + (size_t)(j0 + 6) * K);
    const float4* Wv7 = (const float4*)(W + (size_t)(j0 + 7) * K);
    const float4* gv  = (const float4*)gin;

    float acc[8][8];
#pragma unroll
    for (int j = 0; j < 8; j++)
#pragma unroll
        for (int b = 0; b < 8; b++) acc[j][b] = 0.f;

    for (int k4 = threadIdx.x; k4 < K4; k4 += 256) {
        float4 w[8];
        w[0] = __ldg(Wv0 + k4);
        w[1] = __ldg(Wv1 + k4);
        w[2] = __ldg(Wv2 + k4);
        w[3] = __ldg(Wv3 + k4);
        w[4] = __ldg(Wv4 + k4);
        w[5] = __ldg(Wv5 + k4);
        w[6] = __ldg(Wv6 + k4);
        w[7] = __ldg(Wv7 + k4);
        float4 g[8];
#pragma unroll
        for (int i = 0; i < 8; i++) g[i] = __ldg(gv + (size_t)k4 * 8 + i);
        // g[2*kk+0] = in_t[4*k4+kk][0..3], g[2*kk+1] = in_t[4*k4+kk][4..7]
#pragma unroll
        for (int j = 0; j < 8; j++) {
            float wj[4] = {w[j].x, w[j].y, w[j].z, w[j].w};
#pragma unroll
            for (int kk = 0; kk < 4; kk++) {
                float4 ga = g[kk * 2 + 0];
                float4 gb = g[kk * 2 + 1];
                acc[j][0] = fmaf(wj[kk], ga.x, acc[j][0]);
                acc[j][1] = fmaf(wj[kk], ga.y, acc[j][1]);
                acc[j][2] = fmaf(wj[kk], ga.z, acc[j][2]);
                acc[j][3] = fmaf(wj[kk], ga.w, acc[j][3]);
                acc[j][4] = fmaf(wj[kk], gb.x, acc[j][4]);
                acc[j][5] = fmaf(wj[kk], gb.y, acc[j][5]);
                acc[j][6] = fmaf(wj[kk], gb.z, acc[j][6]);
                acc[j][7] = fmaf(wj[kk], gb.w, acc[j][7]);
            }
        }
    }

    int lane = threadIdx.x & 31;
    int wid  = threadIdx.x >> 5;
#pragma unroll
    for (int j = 0; j < 8; j++) {
#pragma unroll
        for (int b = 0; b < 8; b++) {
            float v = acc[j][b];
#pragma unroll
            for (int o = 16; o > 0; o >>= 1)
                v += __shfl_down_sync(0xffffffffu, v, o);
            if (lane == 0) red[j * 8 + b][wid] = v;
        }
    }
    __syncthreads();
    if (threadIdx.x < 64) {
        int j = threadIdx.x >> 3;
        int b = threadIdx.x & 7;
        float v = 0.f;
#pragma unroll
        for (int w = 0; w < 8; w++) v += red[threadIdx.x][w];
        v += __ldg(&bias[j0 + j]);
        if (do_relu) v = fmaxf(v, 0.f);
        gout[(j0 + j) * 8 + b] = v;
    }
}

// final layer [8,160] @ W4^T [160,10] + b4, then log_softmax per row.
__global__ void final_kernel(const float* __restrict__ W4, const float* __restrict__ b4,
                             float* __restrict__ out) {
    int b    = threadIdx.x >> 5;   // batch (warp id)
    int lane = threadIdx.x & 31;
    float z = -1e30f;
    if (lane < 10) {
        float acc = __ldg(&b4[lane]);
#pragma unroll 8
        for (int k = 0; k < 160; k++)
            acc = fmaf(__ldg(&W4[lane * 160 + k]), d_y3[k * 8 + b], acc);
        z = acc;
    }
    float m = z;
#pragma unroll
    for (int o = 16; o > 0; o >>= 1)
        m = fmaxf(m, __shfl_xor_sync(0xffffffffu, m, o));
    float e = (lane < 10) ? __expf(z - m) : 0.f;
    float ssum = e;
#pragma unroll
    for (int o = 16; o > 0; o >>= 1)
        ssum += __shfl_xor_sync(0xffffffffu, ssum, o);
    if (lane < 10) out[b * 10 + lane] = z - m - __logf(ssum);
}

// ---------------- launch ----------------
extern "C" void kernel_launch(void* const* d_in, const int* in_sizes, int n_in,
                              void* d_out, int out_size) {
    const float* x   = (const float*)d_in[0];
    const float* ew  = (const float*)d_in[1];
    const float* Wr1 = (const float*)d_in[2];
    const float* br1 = (const float*)d_in[3];
    const float* Ws1 = (const float*)d_in[4];
    const float* Wr2 = (const float*)d_in[5];
    const float* br2 = (const float*)d_in[6];
    const float* Ws2 = (const float*)d_in[7];
    const float* W1  = (const float*)d_in[8];
    const float* b1  = (const float*)d_in[9];
    const float* W2  = (const float*)d_in[10];
    const float* b2  = (const float*)d_in[11];
    const float* W3  = (const float*)d_in[12];
    const float* b3  = (const float*)d_in[13];
    const float* W4  = (const float*)d_in[14];
    const float* b4  = (const float*)d_in[15];
    const int*   ei  = (const int*)d_in[16];
    const int* src = ei;
    const int* tgt = ei + N_EDGES;
    float* out = (float*)d_out;

    edge_pass1<<<(N_EDGES / 4 + 255) / 256, 256>>>(src, tgt, ew, x);
    node_kernel<<<(N_NODES + 255) / 256, 256>>>(x, Wr1, br1, Ws1, Wr2, br2, Ws2);
    edge_pass2<<<(N_EDGES / 4 + 255) / 256, 256>>>(src, tgt, ew);
    gemm8v<<<500, 256>>>(W1, b1, 0, 20000, 1);   // 20000 -> 4000
    gemm8v<<<100, 256>>>(W2, b2, 1, 4000, 1);    // 4000 -> 800
    gemm8v<<<20, 256>>>(W3, b3, 2, 800, 1);      // 800 -> 160
    final_kernel<<<1, 256>>>(W4, b4, out);       // 160 -> 10 + log_softmax
}

// round 4
// speedup vs baseline: 1.4787x; 1.0620x over previous
#include <cuda_runtime.h>

#define N_NODES 160000
#define NODES_PER_GRAPH 20000
#define NBATCH 8
#define N_EDGES 5120000
#define HID 16
#define TK 1000
#define GS_PAD 1012

// ---------------- device scratch (no allocation allowed) ----------------
__device__ float d_s1[N_NODES];            // layer-1 scalar aggregation (zero invariant)
__device__ float d_p[N_NODES];             // h . Wr2 per node
__device__ float d_gt[N_NODES];            // h2 transposed: [20000][8]
__device__ float d_part[64000];            // K-split partials (max: 2*4000*8)
__device__ float d_y1[4000 * NBATCH];      // layer outputs, transposed [J][8]
__device__ float d_y2[800 * NBATCH];
__device__ float d_y3[160 * NBATCH];

// ---------------- graph kernels ----------------

// pass 1: s1[tgt] += ew * x[src]
__global__ void edge_pass1(const int* __restrict__ src, const int* __restrict__ tgt,
                           const float* __restrict__ ew, const float* __restrict__ x) {
    int i = blockIdx.x * blockDim.x + threadIdx.x;
    int base = i * 4;
    if (base >= N_EDGES) return;
    int4   s = *(const int4*)(src + base);
    int4   t = *(const int4*)(tgt + base);
    float4 w = *(const float4*)(ew + base);
    atomicAdd(&d_s1[t.x], w.x * __ldg(&x[s.x]));
    atomicAdd(&d_s1[t.y], w.y * __ldg(&x[s.y]));
    atomicAdd(&d_s1[t.z], w.z * __ldg(&x[s.z]));
    atomicAdd(&d_s1[t.w], w.w * __ldg(&x[s.w]));
}

// per node: compute p[n] (for pass 2), init gt with q[n] + br2, re-zero s1
// (keeps the "s1 == 0 at entry" invariant across graph replays).
__global__ void node_kernel(const float* __restrict__ x,
                            const float* __restrict__ Wr1, const float* __restrict__ br1,
                            const float* __restrict__ Ws1, const float* __restrict__ Wr2,
                            const float* __restrict__ br2, const float* __restrict__ Ws2) {
    int n = blockIdx.x * blockDim.x + threadIdx.x;
    if (n >= N_NODES) return;
    float s  = d_s1[n];
    d_s1[n] = 0.f;
    float xv = x[n];
    float pa = 0.f, qa = 0.f;
#pragma unroll
    for (int f = 0; f < HID; f++) {
        float h = fmaf(s, __ldg(&Wr1[f]), fmaf(xv, __ldg(&Ws1[f]), __ldg(&br1[f])));
        h = fmaxf(h, 0.f);
        pa = fmaf(__ldg(&Wr2[f]), h, pa);
        qa = fmaf(__ldg(&Ws2[f]), h, qa);
    }
    d_p[n] = pa;
    unsigned nu = (unsigned)n;
    unsigned b  = nu / NODES_PER_GRAPH;
    unsigned k  = nu - b * NODES_PER_GRAPH;
    d_gt[k * NBATCH + b] = qa + __ldg(&br2[0]);
}

// pass 2: gt[transposed(tgt)] += ew * p[src]
__global__ void edge_pass2(const int* __restrict__ src, const int* __restrict__ tgt,
                           const float* __restrict__ ew) {
    int i = blockIdx.x * blockDim.x + threadIdx.x;
    int base = i * 4;
    if (base >= N_EDGES) return;
    int4   s = *(const int4*)(src + base);
    int4   t = *(const int4*)(tgt + base);
    float4 w = *(const float4*)(ew + base);
#define EP2_ONE(SS, TT, WW)                                            \
    {                                                                  \
        unsigned tu = (unsigned)(TT);                                  \
        unsigned b  = tu / NODES_PER_GRAPH;                            \
        unsigned k  = tu - b * NODES_PER_GRAPH;                        \
        atomicAdd(&d_gt[k * NBATCH + b], (WW) * __ldg(&d_p[SS]));      \
    }
    EP2_ONE(s.x, t.x, w.x);
    EP2_ONE(s.y, t.y, w.y);
    EP2_ONE(s.z, t.z, w.z);
    EP2_ONE(s.w, t.w, w.w);
#undef EP2_ONE
}

// ---- gemm16: 16 rows per block, K-split, g staged in smem ----
// grid.x = (J/16) * nsplit ; block = 256 (8 warps, warp owns 2 rows)
// part[ks*J*8 + j*8 + b] = sum_{k in split ks} W[j,k] * gin_t[k][b]
__global__ void __launch_bounds__(256, 3)
gemm16(const float* __restrict__ W, int gin_sel, int Ktot, int KS, int nsplit, int J) {
    const float* __restrict__ gin = (gin_sel == 0) ? d_gt : d_y1;

    __shared__ float gs[8 * GS_PAD];

    int tid  = threadIdx.x;
    int lane = tid & 31;
    int wid  = tid >> 5;
    int rg   = blockIdx.x / nsplit;
    int ks   = blockIdx.x - rg * nsplit;
    int j0   = rg * 16;
    int k0   = ks * KS;
    int row0 = j0 + wid * 2;

    float acc0[8], acc1[8];
#pragma unroll
    for (int b = 0; b < 8; b++) { acc0[b] = 0.f; acc1[b] = 0.f; }

    for (int tile = 0; tile < KS; tile += TK) {
        __syncthreads();
        // stage 1000 k x 8 b (k-major in gmem) -> gs[b][k] (b-major, padded)
        const float4* gv = (const float4*)(gin + (size_t)(k0 + tile) * 8);
        for (int i = tid; i < TK * 2; i += 256) {
            float4 v = __ldg(gv + i);
            int kk = i >> 1;
            int b0 = (i & 1) * 4;
            gs[(b0 + 0) * GS_PAD + kk] = v.x;
            gs[(b0 + 1) * GS_PAD + kk] = v.y;
            gs[(b0 + 2) * GS_PAD + kk] = v.z;
            gs[(b0 + 3) * GS_PAD + kk] = v.w;
        }
        __syncthreads();

        const float4* Wr0 = (const float4*)(W + (size_t)row0 * Ktot + k0 + tile);
        const float4* Wr1 = (const float4*)(W + (size_t)(row0 + 1) * Ktot + k0 + tile);
        for (int k4 = lane; k4 < TK / 4; k4 += 32) {
            float4 w0 = __ldg(Wr0 + k4);
            float4 w1 = __ldg(Wr1 + k4);
            int kb = k4 * 4;
            float4 gb[8];
#pragma unroll
            for (int b = 0; b < 8; b++)
                gb[b] = *(const float4*)(gs + b * GS_PAD + kb);
#pragma unroll
            for (int b = 0; b < 8; b++) {
                acc0[b] = fmaf(w0.x, gb[b].x, acc0[b]);
                acc0[b] = fmaf(w0.y, gb[b].y, acc0[b]);
                acc0[b] = fmaf(w0.z, gb[b].z, acc0[b]);
                acc0[b] = fmaf(w0.w, gb[b].w, acc0[b]);
                acc1[b] = fmaf(w1.x, gb[b].x, acc1[b]);
                acc1[b] = fmaf(w1.y, gb[b].y, acc1[b]);
                acc1[b] = fmaf(w1.z, gb[b].z, acc1[b]);
                acc1[b] = fmaf(w1.w, gb[b].w, acc1[b]);
            }
        }
    }

    // warp-reduce; lane r*8+b keeps (row r, batch b)
    float mine = 0.f;
#pragma unroll
    for (int b = 0; b < 8; b++) {
        float v = acc0[b];
#pragma unroll
        for (int o = 16; o > 0; o >>= 1) v += __shfl_xor_sync(0xffffffffu, v, o);
        if (lane == b) mine = v;
    }
#pragma unroll
    for (int b = 0; b < 8; b++) {
        float v = acc1[b];
#pragma unroll
        for (int o = 16; o > 0; o >>= 1) v += __shfl_xor_sync(0xffffffffu, v, o);
        if (lane == 8 + b) mine = v;
    }
    if (lane < 16) {
        int r = lane >> 3;
        int b = lane & 7;
        d_part[((size_t)ks * J + (row0 + r)) * 8 + b] = mine;
    }
}

// combine K-split partials: out[j][b] = relu(sum_s part[s][j][b] + bias[j])
__global__ void combine_kernel(const float* __restrict__ bias, int nsplit, int J,
                               int out_sel) {
    float* __restrict__ gout = (out_sel == 0) ? d_y1 : d_y2;
    int i = blockIdx.x * blockDim.x + threadIdx.x;
    if (i >= J * 8) return;
    int j = i >> 3;
    float v = __ldg(&bias[j]);
    for (int s = 0; s < nsplit; s++) v += d_part[(size_t)s * J * 8 + i];
    gout[i] = fmaxf(v, 0.f);
}

// batch-8 GEMV for layer 3 (160 x 800, tiny)
__global__ void gemm8v(const float* __restrict__ W, const float* __restrict__ bias,
                       int K, int do_relu) {
    const float* __restrict__ gin  = d_y2;
    float* __restrict__       gout = d_y3;

    __shared__ float red[64][8];
    int j0 = blockIdx.x * 8;
    int K4 = K >> 2;

    float acc[8][8];
#pragma unroll
    for (int j = 0; j < 8; j++)
#pragma unroll
        for (int b = 0; b < 8; b++) acc[j][b] = 0.f;

    const float4* gv = (const float4*)gin;
    for (int k4 = threadIdx.x; k4 < K4; k4 += 256) {
        float4 w[8];
#pragma unroll
        for (int j = 0; j < 8; j++)
            w[j] = __ldg((const float4*)(W + (size_t)(j0 + j) * K) + k4);
        float4 g[8];
#pragma unroll
        for (int i = 0; i < 8; i++) g[i] = __ldg(gv + (size_t)k4 * 8 + i);
#pragma unroll
        for (int j = 0; j < 8; j++) {
            float wj[4] = {w[j].x, w[j].y, w[j].z, w[j].w};
#pragma unroll
            for (int kk = 0; kk < 4; kk++) {
                float4 ga = g[kk * 2 + 0];
                float4 gb = g[kk * 2 + 1];
                acc[j][0] = fmaf(wj[kk], ga.x, acc[j][0]);
                acc[j][1] = fmaf(wj[kk], ga.y, acc[j][1]);
                acc[j][2] = fmaf(wj[kk], ga.z, acc[j][2]);
                acc[j][3] = fmaf(wj[kk], ga.w, acc[j][3]);
                acc[j][4] = fmaf(wj[kk], gb.x, acc[j][4]);
                acc[j][5] = fmaf(wj[kk], gb.y, acc[j][5]);
                acc[j][6] = fmaf(wj[kk], gb.z, acc[j][6]);
                acc[j][7] = fmaf(wj[kk], gb.w, acc[j][7]);
            }
        }
    }

    int lane = threadIdx.x & 31;
    int wid  = threadIdx.x >> 5;
#pragma unroll
    for (int j = 0; j < 8; j++) {
#pragma unroll
        for (int b = 0; b < 8; b++) {
            float v = acc[j][b];
#pragma unroll
            for (int o = 16; o > 0; o >>= 1)
                v += __shfl_down_sync(0xffffffffu, v, o);
            if (lane == 0) red[j * 8 + b][wid] = v;
        }
    }
    __syncthreads();
    if (threadIdx.x < 64) {
        int j = threadIdx.x >> 3;
        int b = threadIdx.x & 7;
        float v = 0.f;
#pragma unroll
        for (int w = 0; w < 8; w++) v += red[threadIdx.x][w];
        v += __ldg(&bias[j0 + j]);
        if (do_relu) v = fmaxf(v, 0.f);
        gout[(j0 + j) * 8 + b] = v;
    }
}

// final layer [8,160] @ W4^T [160,10] + b4, then log_softmax per row.
__global__ void final_kernel(const float* __restrict__ W4, const float* __restrict__ b4,
                             float* __restrict__ out) {
    int b    = threadIdx.x >> 5;   // batch (warp id)
    int lane = threadIdx.x & 31;
    float z = -1e30f;
    if (lane < 10) {
        float acc = __ldg(&b4[lane]);
#pragma unroll 8
        for (int k = 0; k < 160; k++)
            acc = fmaf(__ldg(&W4[lane * 160 + k]), d_y3[k * 8 + b], acc);
        z = acc;
    }
    float m = z;
#pragma unroll
    for (int o = 16; o > 0; o >>= 1)
        m = fmaxf(m, __shfl_xor_sync(0xffffffffu, m, o));
    float e = (lane < 10) ? __expf(z - m) : 0.f;
    float ssum = e;
#pragma unroll
    for (int o = 16; o > 0; o >>= 1)
        ssum += __shfl_xor_sync(0xffffffffu, ssum, o);
    if (lane < 10) out[b * 10 + lane] = z - m - __logf(ssum);
}

// ---------------- launch ----------------
extern "C" void kernel_launch(void* const* d_in, const int* in_sizes, int n_in,
                              void* d_out, int out_size) {
    const float* x   = (const float*)d_in[0];
    const float* ew  = (const float*)d_in[1];
    const float* Wr1 = (const float*)d_in[2];
    const float* br1 = (const float*)d_in[3];
    const float* Ws1 = (const float*)d_in[4];
    const float* Wr2 = (const float*)d_in[5];
    const float* br2 = (const float*)d_in[6];
    const float* Ws2 = (const float*)d_in[7];
    const float* W1  = (const float*)d_in[8];
    const float* b1  = (const float*)d_in[9];
    const float* W2  = (const float*)d_in[10];
    const float* b2  = (const float*)d_in[11];
    const float* W3  = (const float*)d_in[12];
    const float* b3  = (const float*)d_in[13];
    const float* W4  = (const float*)d_in[14];
    const float* b4  = (const float*)d_in[15];
    const int*   ei  = (const int*)d_in[16];
    const int* src = ei;
    const int* tgt = ei + N_EDGES;
    float* out = (float*)d_out;

    edge_pass1<<<(N_EDGES / 4 + 255) / 256, 256>>>(src, tgt, ew, x);
    node_kernel<<<(N_NODES + 255) / 256, 256>>>(x, Wr1, br1, Ws1, Wr2, br2, Ws2);
    edge_pass2<<<(N_EDGES / 4 + 255) / 256, 256>>>(src, tgt, ew);

    // layer 1: 20000 -> 4000 ; 250 row-groups x 2 K-splits (KS=10000)
    gemm16<<<500, 256>>>(W1, 0, 20000, 10000, 2, 4000);
    combine_kernel<<<(4000 * 8 + 255) / 256, 256>>>(b1, 2, 4000, 0);

    // layer 2: 4000 -> 800 ; 50 row-groups x 4 K-splits (KS=1000)
    gemm16<<<200, 256>>>(W2, 1, 4000, 1000, 4, 800);
    combine_kernel<<<(800 * 8 + 255) / 256, 256>>>(b2, 4, 800, 1);

    // layer 3: 800 -> 160
    gemm8v<<<20, 256>>>(W3, b3, 800, 1);
    final_kernel<<<1, 256>>>(W4, b4, out);
}

// round 5
// speedup vs baseline: 1.9170x; 1.2963x over previous
#include <cuda_runtime.h>

#define N_NODES 160000
#define NODES_PER_GRAPH 20000
#define NBATCH 8
#define N_EDGES 5120000
#define HID 16
#define TKILE 1024

// ---------------- device scratch (no allocation allowed) ----------------
__device__ float d_s1[N_NODES];            // layer-1 scalar aggregation (zero invariant)
__device__ float d_p[N_NODES];             // h . Wr2 per node
__device__ float d_gt[N_NODES];            // h2 transposed: [20000][8]
__device__ float d_part[64000];            // K-split partials
__device__ float d_y1[4000 * NBATCH];
__device__ float d_y2[800 * NBATCH];
__device__ float d_y3[160 * NBATCH];

// ---------------- graph kernels ----------------

__global__ void edge_pass1(const int* __restrict__ src, const int* __restrict__ tgt,
                           const float* __restrict__ ew, const float* __restrict__ x) {
    int i = blockIdx.x * blockDim.x + threadIdx.x;
    int base = i * 4;
    if (base >= N_EDGES) return;
    int4   s = *(const int4*)(src + base);
    int4   t = *(const int4*)(tgt + base);
    float4 w = *(const float4*)(ew + base);
    atomicAdd(&d_s1[t.x], w.x * __ldg(&x[s.x]));
    atomicAdd(&d_s1[t.y], w.y * __ldg(&x[s.y]));
    atomicAdd(&d_s1[t.z], w.z * __ldg(&x[s.z]));
    atomicAdd(&d_s1[t.w], w.w * __ldg(&x[s.w]));
}

__global__ void node_kernel(const float* __restrict__ x,
                            const float* __restrict__ Wr1, const float* __restrict__ br1,
                            const float* __restrict__ Ws1, const float* __restrict__ Wr2,
                            const float* __restrict__ br2, const float* __restrict__ Ws2) {
    int n = blockIdx.x * blockDim.x + threadIdx.x;
    if (n >= N_NODES) return;
    float s  = d_s1[n];
    d_s1[n] = 0.f;   // keep "s1 == 0 at entry" invariant across graph replays
    float xv = x[n];
    float pa = 0.f, qa = 0.f;
#pragma unroll
    for (int f = 0; f < HID; f++) {
        float h = fmaf(s, __ldg(&Wr1[f]), fmaf(xv, __ldg(&Ws1[f]), __ldg(&br1[f])));
        h = fmaxf(h, 0.f);
        pa = fmaf(__ldg(&Wr2[f]), h, pa);
        qa = fmaf(__ldg(&Ws2[f]), h, qa);
    }
    d_p[n] = pa;
    unsigned nu = (unsigned)n;
    unsigned b  = nu / NODES_PER_GRAPH;
    unsigned k  = nu - b * NODES_PER_GRAPH;
    d_gt[k * NBATCH + b] = qa + __ldg(&br2[0]);
}

__global__ void edge_pass2(const int* __restrict__ src, const int* __restrict__ tgt,
                           const float* __restrict__ ew) {
    int i = blockIdx.x * blockDim.x + threadIdx.x;
    int base = i * 4;
    if (base >= N_EDGES) return;
    int4   s = *(const int4*)(src + base);
    int4   t = *(const int4*)(tgt + base);
    float4 w = *(const float4*)(ew + base);
#define EP2_ONE(SS, TT, WW)                                            \
    {                                                                  \
        unsigned tu = (unsigned)(TT);                                  \
        unsigned b  = tu / NODES_PER_GRAPH;                            \
        unsigned k  = tu - b * NODES_PER_GRAPH;                        \
        atomicAdd(&d_gt[k * NBATCH + b], (WW) * __ldg(&d_p[SS]));      \
    }
    EP2_ONE(s.x, t.x, w.x);
    EP2_ONE(s.y, t.y, w.y);
    EP2_ONE(s.z, t.z, w.z);
    EP2_ONE(s.w, t.w, w.w);
#undef EP2_ONE
}

// ---------------- packed f32x2 helpers ----------------
__device__ __forceinline__ unsigned long long pack2(float v) {
    unsigned long long r;
    unsigned u = __float_as_uint(v);
    asm("mov.b64 %0, {%1, %1};" : "=l"(r) : "r"(u));
    return r;
}
__device__ __forceinline__ unsigned long long fma2(unsigned long long a,
                                                   unsigned long long b,
                                                   unsigned long long c) {
    unsigned long long d;
    asm("fma.rn.f32x2 %0, %1, %2, %3;" : "=l"(d) : "l"(a), "l"(b), "l"(c));
    return d;
}
__device__ __forceinline__ unsigned long long add2(unsigned long long a,
                                                   unsigned long long b) {
    unsigned long long d;
    asm("add.rn.f32x2 %0, %1, %2;" : "=l"(d) : "l"(a), "l"(b));
    return d;
}
__device__ __forceinline__ float lo2(unsigned long long a) {
    unsigned x, y;
    asm("mov.b64 {%0, %1}, %2;" : "=r"(x), "=r"(y) : "l"(a));
    return __uint_as_float(x);
}
__device__ __forceinline__ float hi2(unsigned long long a) {
    unsigned x, y;
    asm("mov.b64 {%0, %1}, %2;" : "=r"(x), "=r"(y) : "l"(a));
    return __uint_as_float(y);
}

// ---- gemm32: 32 rows/block (8 warps x 4 rows), K-split, packed f32x2 ----
// part[ks*J*8 + j*8 + b] = sum_{k in split ks} W[j,k] * gin_t[k][b]
__global__ void __launch_bounds__(256, 2)
gemm32(const float* __restrict__ W, int gin_sel, int Ktot, int KS, int nsplit, int J) {
    const float* __restrict__ gin = (gin_sel == 0) ? d_gt : d_y1;

    __shared__ float2 gs[4][TKILE];  // plane-major: gs[b/2][k] = {g[k][2p], g[k][2p+1]}

    int tid  = threadIdx.x;
    int lane = tid & 31;
    int wid  = tid >> 5;
    int rg   = blockIdx.x / nsplit;
    int ks   = blockIdx.x - rg * nsplit;
    int j0   = rg * 32;
    int row0 = j0 + wid * 4;
    int k0   = ks * KS;
    int kend = min(k0 + KS, Ktot);

    unsigned long long acc[4][4];
#pragma unroll
    for (int r = 0; r < 4; r++)
#pragma unroll
        for (int p = 0; p < 4; p++) acc[r][p] = 0ull;

    for (int kt = k0; kt < kend; kt += TKILE) {
        int kv = min(TKILE, kend - kt);
        __syncthreads();
        // stage g tile: [k][8] gmem -> plane-major smem, zero-pad beyond kv
        for (int k = tid; k < TKILE; k += 256) {
            float4 a, b;
            if (k < kv) {
                a = __ldg((const float4*)(gin + (size_t)(kt + k) * 8));
                b = __ldg((const float4*)(gin + (size_t)(kt + k) * 8 + 4));
            } else {
                a = make_float4(0.f, 0.f, 0.f, 0.f);
                b = a;
            }
            gs[0][k] = make_float2(a.x, a.y);
            gs[1][k] = make_float2(a.z, a.w);
            gs[2][k] = make_float2(b.x, b.y);
            gs[3][k] = make_float2(b.z, b.w);
        }
        __syncthreads();

        int iters = (kv + 127) >> 7;
        for (int it = 0; it < iters; it++) {
            int kb = it * 128 + lane;  // local k for j=0 (j adds 32 each)

            // 16 W loads (coalesced LDG.32), guarded against split tail
            float w[4][4];
#pragma unroll
            for (int r = 0; r < 4; r++) {
                const float* Wr = W + (size_t)(row0 + r) * Ktot + kt;
#pragma unroll
                for (int j = 0; j < 4; j++) {
                    int kk = kb + 32 * j;
                    w[r][j] = (kk < kv) ? __ldg(Wr + kk) : 0.f;
                }
            }
            // 16 conflict-free LDS.64 (zero-padded smem, always in-bounds)
            unsigned long long g[4][4];
#pragma unroll
            for (int j = 0; j < 4; j++) {
                int kk = kb + 32 * j;
#pragma unroll
                for (int p = 0; p < 4; p++)
                    g[j][p] = *(const unsigned long long*)&gs[p][kk];
            }
            // 64 packed FMAs
#pragma unroll
            for (int r = 0; r < 4; r++)
#pragma unroll
                for (int j = 0; j < 4; j++) {
                    unsigned long long wp = pack2(w[r][j]);
#pragma unroll
                    for (int p = 0; p < 4; p++)
                        acc[r][p] = fma2(wp, g[j][p], acc[r][p]);
                }
        }
    }

    // cross-lane reduction of the 16 packed accumulators
    float outv = 0.f;
#pragma unroll
    for (int r = 0; r < 4; r++)
#pragma unroll
        for (int p = 0; p < 4; p++) {
            unsigned long long v = acc[r][p];
#pragma unroll
            for (int o = 16; o > 0; o >>= 1)
                v = add2(v, __shfl_xor_sync(0xffffffffu, v, o));
            if (lane == r * 8 + 2 * p)     outv = lo2(v);
            if (lane == r * 8 + 2 * p + 1) outv = hi2(v);
        }
    {
        int r = lane >> 3;
        int b = lane & 7;
        d_part[((size_t)ks * J + (row0 + r)) * 8 + b] = outv;
    }
}

// combine K-split partials: out[j][b] = relu(sum_s part[s][j][b] + bias[j])
__global__ void combine_kernel(const float* __restrict__ bias, int nsplit, int J,
                               int out_sel) {
    float* __restrict__ gout = (out_sel == 0) ? d_y1 : d_y2;
    int i = blockIdx.x * blockDim.x + threadIdx.x;
    if (i >= J * 8) return;
    int j = i >> 3;
    float v = __ldg(&bias[j]);
    for (int s = 0; s < nsplit; s++) v += d_part[(size_t)s * J * 8 + i];
    gout[i] = fmaxf(v, 0.f);
}

// batch-8 GEMV for layer 3 (160 x 800, tiny)
__global__ void gemm8v(const float* __restrict__ W, const float* __restrict__ bias,
                       int K, int do_relu) {
    const float* __restrict__ gin  = d_y2;
    float* __restrict__       gout = d_y3;

    __shared__ float red[64][8];
    int j0 = blockIdx.x * 8;
    int K4 = K >> 2;

    float acc[8][8];
#pragma unroll
    for (int j = 0; j < 8; j++)
#pragma unroll
        for (int b = 0; b < 8; b++) acc[j][b] = 0.f;

    const float4* gv = (const float4*)gin;
    for (int k4 = threadIdx.x; k4 < K4; k4 += 256) {
        float4 w[8];
#pragma unroll
        for (int j = 0; j < 8; j++)
            w[j] = __ldg((const float4*)(W + (size_t)(j0 + j) * K) + k4);
        float4 g[8];
#pragma unroll
        for (int i = 0; i < 8; i++) g[i] = __ldg(gv + (size_t)k4 * 8 + i);
#pragma unroll
        for (int j = 0; j < 8; j++) {
            float wj[4] = {w[j].x, w[j].y, w[j].z, w[j].w};
#pragma unroll
            for (int kk = 0; kk < 4; kk++) {
                float4 ga = g[kk * 2 + 0];
                float4 gb = g[kk * 2 + 1];
                acc[j][0] = fmaf(wj[kk], ga.x, acc[j][0]);
                acc[j][1] = fmaf(wj[kk], ga.y, acc[j][1]);
                acc[j][2] = fmaf(wj[kk], ga.z, acc[j][2]);
                acc[j][3] = fmaf(wj[kk], ga.w, acc[j][3]);
                acc[j][4] = fmaf(wj[kk], gb.x, acc[j][4]);
                acc[j][5] = fmaf(wj[kk], gb.y, acc[j][5]);
                acc[j][6] = fmaf(wj[kk], gb.z, acc[j][6]);
                acc[j][7] = fmaf(wj[kk], gb.w, acc[j][7]);
            }
        }
    }

    int lane = threadIdx.x & 31;
    int wid  = threadIdx.x >> 5;
#pragma unroll
    for (int j = 0; j < 8; j++) {
#pragma unroll
        for (int b = 0; b < 8; b++) {
            float v = acc[j][b];
#pragma unroll
            for (int o = 16; o > 0; o >>= 1)
                v += __shfl_down_sync(0xffffffffu, v, o);
            if (lane == 0) red[j * 8 + b][wid] = v;
        }
    }
    __syncthreads();
    if (threadIdx.x < 64) {
        int j = threadIdx.x >> 3;
        int b = threadIdx.x & 7;
        float v = 0.f;
#pragma unroll
        for (int w = 0; w < 8; w++) v += red[threadIdx.x][w];
        v += __ldg(&bias[j0 + j]);
        if (do_relu) v = fmaxf(v, 0.f);
        gout[(j0 + j) * 8 + b] = v;
    }
}

// final layer [8,160] @ W4^T [160,10] + b4, then log_softmax per row.
__global__ void final_kernel(const float* __restrict__ W4, const float* __restrict__ b4,
                             float* __restrict__ out) {
    int b    = threadIdx.x >> 5;
    int lane = threadIdx.x & 31;
    float z = -1e30f;
    if (lane < 10) {
        float acc = __ldg(&b4[lane]);
#pragma unroll 8
        for (int k = 0; k < 160; k++)
            acc = fmaf(__ldg(&W4[lane * 160 + k]), d_y3[k * 8 + b], acc);
        z = acc;
    }
    float m = z;
#pragma unroll
    for (int o = 16; o > 0; o >>= 1)
        m = fmaxf(m, __shfl_xor_sync(0xffffffffu, m, o));
    float e = (lane < 10) ? __expf(z - m) : 0.f;
    float ssum = e;
#pragma unroll
    for (int o = 16; o > 0; o >>= 1)
        ssum += __shfl_xor_sync(0xffffffffu, ssum, o);
    if (lane < 10) out[b * 10 + lane] = z - m - __logf(ssum);
}

// ---------------- launch ----------------
extern "C" void kernel_launch(void* const* d_in, const int* in_sizes, int n_in,
                              void* d_out, int out_size) {
    const float* x   = (const float*)d_in[0];
    const float* ew  = (const float*)d_in[1];
    const float* Wr1 = (const float*)d_in[2];
    const float* br1 = (const float*)d_in[3];
    const float* Ws1 = (const float*)d_in[4];
    const float* Wr2 = (const float*)d_in[5];
    const float* br2 = (const float*)d_in[6];
    const float* Ws2 = (const float*)d_in[7];
    const float* W1  = (const float*)d_in[8];
    const float* b1  = (const float*)d_in[9];
    const float* W2  = (const float*)d_in[10];
    const float* b2  = (const float*)d_in[11];
    const float* W3  = (const float*)d_in[12];
    const float* b3  = (const float*)d_in[13];
    const float* W4  = (const float*)d_in[14];
    const float* b4  = (const float*)d_in[15];
    const int*   ei  = (const int*)d_in[16];
    const int* src = ei;
    const int* tgt = ei + N_EDGES;
    float* out = (float*)d_out;

    edge_pass1<<<(N_EDGES / 4 + 255) / 256, 256>>>(src, tgt, ew, x);
    node_kernel<<<(N_NODES + 255) / 256, 256>>>(x, Wr1, br1, Ws1, Wr2, br2, Ws2);
    edge_pass2<<<(N_EDGES / 4 + 255) / 256, 256>>>(src, tgt, ew);

    // layer 1: 20000 -> 4000 ; 125 row-groups x 2 K-splits (KS=10000)
    gemm32<<<250, 256>>>(W1, 0, 20000, 10000, 2, 4000);
    combine_kernel<<<(4000 * 8 + 255) / 256, 256>>>(b1, 2, 4000, 0);

    // layer 2: 4000 -> 800 ; 25 row-groups x 8 K-splits (KS=500)
    gemm32<<<200, 256>>>(W2, 1, 4000, 500, 8, 800);
    combine_kernel<<<(800 * 8 + 255) / 256, 256>>>(b2, 8, 800, 1);

    // layer 3: 800 -> 160
    gemm8v<<<20, 256>>>(W3, b3, 800, 1);
    final_kernel<<<1, 256>>>(W4, b4, out);
}